// round 8
// baseline (speedup 1.0000x reference)
#include <cuda_runtime.h>
#include <cstdint>

// Output = constant 1.0f everywhere, [32,128,4096] fp32 = 64 MiB
// (reference's quantum-circuit ops are identity stubs; probs.sum() == 1.0).
//
// Measured (R1-R7): L2-resident write stream pinned at the L2 write-port
// ceiling (~5.9 TB/s, ~50% L2 SOL, path-independent: 4 STG shapes + TMA bulk
// all land 11.4-13.1us ncu; floor ~10.8us). Final tuning axis: per-CTA grain.
// 16 KiB/CTA (4096 x 256 x 4 STG.E.128) gives the work distributor the finest
// load-balance granularity -> smallest tail, while 32 warps x 4 independent
// STG.128 per SM keeps the store queue full.

__global__ __launch_bounds__(256) void fill_ones_kernel(float4* __restrict__ out) {
    const float4 v = make_float4(1.0f, 1.0f, 1.0f, 1.0f);
    // Each block owns 256*4 = 1024 consecutive float4 (16 KiB).
    // Thread t writes block_base + t + k*256: each warp store is a
    // contiguous 512B segment -> full-line L2 writes.
    float4* p = out + (size_t)blockIdx.x * 1024 + threadIdx.x;
    #pragma unroll
    for (int k = 0; k < 4; k++) {
        p[k * 256] = v;
    }
}

extern "C" void kernel_launch(void* const* d_in, const int* in_sizes, int n_in,
                              void* d_out, int out_size) {
    (void)d_in; (void)in_sizes; (void)n_in; (void)out_size;
    // 16777216 floats = 4194304 float4 = 4096 blocks * 256 thr * 4
    fill_ones_kernel<<<4096, 256>>>(reinterpret_cast<float4*>(d_out));
}

// round 9
// speedup vs baseline: 1.0201x; 1.0201x over previous
#include <cuda_runtime.h>
#include <cstdint>

// Output = constant 1.0f everywhere, [32,128,4096] fp32 = 64 MiB
// (reference's quantum-circuit ops are identity stubs; probs.sum() == 1.0).
//
// Measured (R1-R8): L2-resident write stream at the L2 write-port ceiling
// (~5.9-6.1 TB/s, ~50-52% L2 SOL, path-independent). Grain trend confirmed:
// ncu 11.39us @32KiB/CTA -> 11.01us @16KiB/CTA (better tail load-balance).
// This round: 8 KiB/CTA = 8192 blocks x 256 thr x 2 STG.E.128, halving tail
// granularity again while keeping per-SM store MLP ample.

__global__ __launch_bounds__(256) void fill_ones_kernel(float4* __restrict__ out) {
    const float4 v = make_float4(1.0f, 1.0f, 1.0f, 1.0f);
    // Each block owns 256*2 = 512 consecutive float4 (8 KiB).
    // Warp stores are contiguous 512B segments -> full-line L2 writes.
    float4* p = out + (size_t)blockIdx.x * 512 + threadIdx.x;
    p[0]   = v;
    p[256] = v;
}

extern "C" void kernel_launch(void* const* d_in, const int* in_sizes, int n_in,
                              void* d_out, int out_size) {
    (void)d_in; (void)in_sizes; (void)n_in; (void)out_size;
    // 16777216 floats = 4194304 float4 = 8192 blocks * 256 thr * 2
    fill_ones_kernel<<<8192, 256>>>(reinterpret_cast<float4*>(d_out));
}